// round 12
// baseline (speedup 1.0000x reference)
#include <cuda_runtime.h>
#include <math.h>

#define N_NODES   100000
#define N_EDGES   1600000
#define D         128
#define N_GRAPHS  128
#define N_CLASSES 10

typedef unsigned long long ull;

// packed dual-FMA: acc(2xf32) += a(2xf32) * b(2xf32)
#define FMA2(acc, a, b) \
    asm("fma.rn.f32x2 %0, %1, %2, %0;" : "+l"(acc) : "l"(a), "l"(b))

// ---------------- scratch (static device globals; no allocs) ----------------
__device__ __align__(16) float g_h  [(size_t)N_NODES * D];   // ping buffer
__device__ __align__(16) float g_buf[(size_t)N_NODES * D];   // pong buffer
__device__ __align__(16) float g_wp [2][D * D];              // k-pair-packed W0,W1
__device__ float g_dinv[N_NODES];
__device__ int   g_degi[N_NODES];
__device__ int   g_off [N_NODES + 1];
__device__ int   g_cur [N_NODES];
__device__ __align__(16) int2 g_csr[N_EDGES];                // {src, norm bits}
__device__ __align__(16) float g_sums[N_GRAPHS * D];
__device__ int   g_end [N_GRAPHS];
__device__ int   g_bsum[391];
__device__ int   g_bpre[391];

// ---------------- setup: zero + graph boundaries (independent work) -------
__global__ void zb_kernel(const int* __restrict__ batch) {
    int i = blockIdx.x * blockDim.x + threadIdx.x;
    if (i < N_NODES)      g_degi[i] = 0;
    if (i < N_GRAPHS * D) g_sums[i] = 0.0f;
    if (i < N_NODES) {
        int b  = batch[i];
        int bn = (i + 1 < N_NODES) ? batch[i + 1] : N_GRAPHS;
        for (int g = b; g < bn; g++) g_end[g] = i + 1;
        if (i == 0)
            for (int g = 0; g < b; g++) g_end[g] = 0;
    }
}

// histogram of dst, 2 edges/thread (vector load)
__global__ void hist_kernel(const int* __restrict__ dst) {
    int e2 = blockIdx.x * blockDim.x + threadIdx.x;
    if (e2 >= N_EDGES / 2) return;
    int2 d = ((const int2*)dst)[e2];
    atomicAdd(&g_degi[d.x], 1);
    atomicAdd(&g_degi[d.y], 1);
}

// ---- 3-phase parallel scan over g_degi -> g_off / g_cur (+dinv fold) ----
__global__ void blockred_kernel() {           // grid 391 x 256
    __shared__ int sh[256];
    int t = threadIdx.x;
    int i = blockIdx.x * 256 + t;
    sh[t] = (i < N_NODES) ? g_degi[i] : 0;
    __syncthreads();
    for (int ofs = 128; ofs > 0; ofs >>= 1) {
        if (t < ofs) sh[t] += sh[t + ofs];
        __syncthreads();
    }
    if (t == 0) g_bsum[blockIdx.x] = sh[0];
}

__global__ void bscan_kernel() {              // 1 block x 512
    __shared__ int sh[512];
    int t = threadIdx.x;
    int v = (t < 391) ? g_bsum[t] : 0;
    sh[t] = v;
    __syncthreads();
    for (int ofs = 1; ofs < 512; ofs <<= 1) {
        int u = (t >= ofs) ? sh[t - ofs] : 0;
        __syncthreads();
        sh[t] += u;
        __syncthreads();
    }
    if (t < 391) g_bpre[t] = sh[t] - v;       // exclusive prefix of block sums
    if (t == 0) g_off[N_NODES] = N_EDGES;
}

__global__ void blockscan_kernel() {          // grid 391 x 256; also dinv
    __shared__ int sh[256];
    int t = threadIdx.x;
    int i = blockIdx.x * 256 + t;
    int v = (i < N_NODES) ? g_degi[i] : 0;
    sh[t] = v;
    __syncthreads();
    for (int ofs = 1; ofs < 256; ofs <<= 1) {
        int u = (t >= ofs) ? sh[t - ofs] : 0;
        __syncthreads();
        sh[t] += u;
        __syncthreads();
    }
    if (i < N_NODES) {
        int excl = sh[t] - v + g_bpre[blockIdx.x];
        g_off[i] = excl;
        g_cur[i] = excl;
        g_dinv[i] = rsqrtf((float)v + 1.0f);
    }
}

// place edges into CSR, 2 edges/thread (vector loads)
__global__ void place_kernel(const int* __restrict__ ei) {
    int e2 = blockIdx.x * blockDim.x + threadIdx.x;
    if (e2 >= N_EDGES / 2) return;
    int2 s = ((const int2*)ei)[e2];
    int2 d = ((const int2*)(ei + N_EDGES))[e2];
    int p0 = atomicAdd(&g_cur[d.x], 1);
    g_csr[p0] = make_int2(s.x, __float_as_int(g_dinv[s.x] * g_dinv[d.x]));
    int p1 = atomicAdd(&g_cur[d.y], 1);
    g_csr[p1] = make_int2(s.y, __float_as_int(g_dinv[s.y] * g_dinv[d.y]));
}

// ---------------- W pack (both weights in one launch) ---------------------
// WP[(k/2)*2D + c*2 + (k&1)] = W[k][c]
__global__ void pack2_kernel(const float* __restrict__ W0,
                             const float* __restrict__ W1,
                             float* __restrict__ WP) {
    int i = blockIdx.x * blockDim.x + threadIdx.x;   // over 2*D*D
    if (i >= 2 * D * D) return;
    const float* W = (i < D * D) ? W0 : W1;
    int ii = (i < D * D) ? i : i - D * D;
    int base = (i < D * D) ? 0 : D * D;
    int k = ii >> 7, c = ii & 127;
    WP[base + (k >> 1) * (2 * D) + c * 2 + (k & 1)] = W[ii];
}

// ---------------- GEMM+bias+relu: Y = relu(X @ W + b) ---------------------
__global__ void gemm_br_kernel(const float* __restrict__ X,
                               const float* __restrict__ WP,
                               const float* __restrict__ b,
                               float* __restrict__ Y) {
    int block_row = blockIdx.x * 32;
    int lane = threadIdx.x & 31;
    int rt   = threadIdx.x >> 5;

    ull acc2[4][4];
#pragma unroll
    for (int j = 0; j < 4; j++)
#pragma unroll
        for (int c = 0; c < 4; c++) acc2[j][c] = 0ULL;

    for (int k = 0; k < D; k += 4) {
        ulonglong2 w0  = *(const ulonglong2*)&WP[(k >> 1) * (2 * D) + lane * 8];
        ulonglong2 w0b = *(const ulonglong2*)&WP[(k >> 1) * (2 * D) + lane * 8 + 4];
        ulonglong2 w1  = *(const ulonglong2*)&WP[((k >> 1) + 1) * (2 * D) + lane * 8];
        ulonglong2 w1b = *(const ulonglong2*)&WP[((k >> 1) + 1) * (2 * D) + lane * 8 + 4];
#pragma unroll
        for (int j = 0; j < 4; j++) {
            int r = block_row + rt + 8 * j;
            ulonglong2 xa = *(const ulonglong2*)&X[(size_t)r * D + k];
            FMA2(acc2[j][0], xa.x, w0.x);
            FMA2(acc2[j][1], xa.x, w0.y);
            FMA2(acc2[j][2], xa.x, w0b.x);
            FMA2(acc2[j][3], xa.x, w0b.y);
            FMA2(acc2[j][0], xa.y, w1.x);
            FMA2(acc2[j][1], xa.y, w1.y);
            FMA2(acc2[j][2], xa.y, w1b.x);
            FMA2(acc2[j][3], xa.y, w1b.y);
        }
    }
    float4 bb = ((const float4*)b)[lane];
    float bv[4] = {bb.x, bb.y, bb.z, bb.w};
#pragma unroll
    for (int j = 0; j < 4; j++) {
        float o[4];
#pragma unroll
        for (int c = 0; c < 4; c++) {
            unsigned lo, hi;
            asm("mov.b64 {%0,%1}, %2;" : "=r"(lo), "=r"(hi) : "l"(acc2[j][c]));
            o[c] = fmaxf(__uint_as_float(lo) + __uint_as_float(hi) + bv[c], 0.0f);
        }
        int r = block_row + rt + 8 * j;
        *(float4*)&Y[(size_t)r * D + lane * 4] =
            make_float4(o[0], o[1], o[2], o[3]);
    }
}

// ---------------- pure gather: dinv^2*x_node + sum norm*x_src -------------
__device__ __forceinline__ float4 f4fma(float4 a, float n, float4 v) {
    a.x += n * v.x; a.y += n * v.y; a.z += n * v.z; a.w += n * v.w;
    return a;
}
__device__ __forceinline__ float4 f4add(float4 a, float4 b) {
    a.x += b.x; a.y += b.y; a.z += b.z; a.w += b.w;
    return a;
}

__device__ __forceinline__ float4 gather_body(const float* __restrict__ X,
                                              int node, int lane) {
    float di = g_dinv[node];
    float s  = di * di;
    float4 a0 = ((const float4*)(X + (size_t)node * D))[lane];
    a0.x *= s; a0.y *= s; a0.z *= s; a0.w *= s;
    float4 a1 = make_float4(0.f, 0.f, 0.f, 0.f);
    float4 a2 = make_float4(0.f, 0.f, 0.f, 0.f);
    float4 a3 = make_float4(0.f, 0.f, 0.f, 0.f);

    int j = g_off[node], end = g_off[node + 1];

    // peel one edge to align j to even (int4 csr loads need 16B alignment)
    if ((j & 1) && j < end) {
        int2 e = g_csr[j];
        float4 v = ((const float4*)(X + (size_t)e.x * D))[lane];
        a1 = f4fma(a1, __int_as_float(e.y), v);
        j++;
    }
    // 8-edge batches: 4 int4 csr loads + 8 independent feature loads,
    // 4 separate accumulator chains (depth 2 per batch each)
    for (; j + 8 <= end; j += 8) {
        int4 c01 = *(const int4*)&g_csr[j + 0];
        int4 c23 = *(const int4*)&g_csr[j + 2];
        int4 c45 = *(const int4*)&g_csr[j + 4];
        int4 c67 = *(const int4*)&g_csr[j + 6];
        float4 v0 = ((const float4*)(X + (size_t)c01.x * D))[lane];
        float4 v1 = ((const float4*)(X + (size_t)c01.z * D))[lane];
        float4 v2 = ((const float4*)(X + (size_t)c23.x * D))[lane];
        float4 v3 = ((const float4*)(X + (size_t)c23.z * D))[lane];
        float4 v4 = ((const float4*)(X + (size_t)c45.x * D))[lane];
        float4 v5 = ((const float4*)(X + (size_t)c45.z * D))[lane];
        float4 v6 = ((const float4*)(X + (size_t)c67.x * D))[lane];
        float4 v7 = ((const float4*)(X + (size_t)c67.z * D))[lane];
        a0 = f4fma(a0, __int_as_float(c01.y), v0);
        a1 = f4fma(a1, __int_as_float(c01.w), v1);
        a2 = f4fma(a2, __int_as_float(c23.y), v2);
        a3 = f4fma(a3, __int_as_float(c23.w), v3);
        a0 = f4fma(a0, __int_as_float(c45.y), v4);
        a1 = f4fma(a1, __int_as_float(c45.w), v5);
        a2 = f4fma(a2, __int_as_float(c67.y), v6);
        a3 = f4fma(a3, __int_as_float(c67.w), v7);
    }
    // 2-edge remainder (aligned int4 pairs)
    for (; j + 2 <= end; j += 2) {
        int4 c01 = *(const int4*)&g_csr[j];
        float4 v0 = ((const float4*)(X + (size_t)c01.x * D))[lane];
        float4 v1 = ((const float4*)(X + (size_t)c01.z * D))[lane];
        a0 = f4fma(a0, __int_as_float(c01.y), v0);
        a1 = f4fma(a1, __int_as_float(c01.w), v1);
    }
    if (j < end) {
        int2 e = g_csr[j];
        float4 v = ((const float4*)(X + (size_t)e.x * D))[lane];
        a2 = f4fma(a2, __int_as_float(e.y), v);
    }
    return f4add(f4add(a0, a1), f4add(a2, a3));
}

__global__ void gather_kernel(const float* __restrict__ X,
                              float* __restrict__ out) {
    int node = (blockIdx.x * blockDim.x + threadIdx.x) >> 5;
    if (node >= N_NODES) return;
    int lane = threadIdx.x & 31;
    float4 acc = gather_body(X, node, lane);
    ((float4*)(out + (size_t)node * D))[lane] = acc;
}

// last layer: gather on PRE-GEMM features, pooled into g_sums (linearity)
__global__ void gather_pool_kernel(const float* __restrict__ X,
                                   const int* __restrict__ batch) {
    int node = (blockIdx.x * blockDim.x + threadIdx.x) >> 5;
    if (node >= N_NODES) return;
    int lane = threadIdx.x & 31;
    float4 acc = gather_body(X, node, lane);
    int g = batch[node];
    float* p = &g_sums[g * D + lane * 4];
    atomicAdd(p + 0, acc.x);
    atomicAdd(p + 1, acc.y);
    atomicAdd(p + 2, acc.z);
    atomicAdd(p + 3, acc.w);
}

// ---------------- head: S·W2/cnt + b2 -> linear -> softmax ----------------
__global__ void head_kernel(const float* __restrict__ W2,
                            const float* __restrict__ b2,
                            const float* __restrict__ lin_W,
                            const float* __restrict__ lin_b,
                            float* __restrict__ out) {
    __shared__ float sp[D];
    __shared__ float sl[N_CLASSES];
    int g = blockIdx.x;
    int c = threadIdx.x;
    int cnt = g_end[g] - (g > 0 ? g_end[g - 1] : 0);
    float inv = 1.0f / fmaxf((float)cnt, 1.0f);

    float acc = 0.0f;
    for (int k = 0; k < D; k++)
        acc += g_sums[g * D + k] * W2[k * D + c];
    sp[c] = acc * inv + b2[c];
    __syncthreads();

    if (c < N_CLASSES) {
        float l = lin_b[c];
        for (int k = 0; k < D; k++)
            l += sp[k] * lin_W[k * N_CLASSES + c];
        sl[c] = l;
    }
    __syncthreads();

    if (c == 0) {
        float m = sl[0];
#pragma unroll
        for (int j = 1; j < N_CLASSES; j++) m = fmaxf(m, sl[j]);
        float e[N_CLASSES], ssum = 0.0f;
#pragma unroll
        for (int j = 0; j < N_CLASSES; j++) { e[j] = expf(sl[j] - m); ssum += e[j]; }
        float isum = 1.0f / ssum;
#pragma unroll
        for (int j = 0; j < N_CLASSES; j++)
            out[g * N_CLASSES + j] = e[j] * isum;
    }
}

// ---------------- launch ----------------
extern "C" void kernel_launch(void* const* d_in, const int* in_sizes, int n_in,
                              void* d_out, int out_size) {
    const float* x     = (const float*)d_in[0];
    const int*   ei    = (const int*)d_in[1];    // int32 (JAX x64 disabled)
    const int*   batch = (const int*)d_in[2];
    const float* W0    = (const float*)d_in[3];
    const float* b0    = (const float*)d_in[4];
    const float* W1    = (const float*)d_in[5];
    const float* b1    = (const float*)d_in[6];
    const float* W2    = (const float*)d_in[7];
    const float* b2    = (const float*)d_in[8];
    const float* lW    = (const float*)d_in[9];
    const float* lb    = (const float*)d_in[10];
    float* out = (float*)d_out;

    void *ph, *pb, *pw;
    cudaGetSymbolAddress(&ph, g_h);
    cudaGetSymbolAddress(&pb, g_buf);
    cudaGetSymbolAddress(&pw, g_wp);
    float* H  = (float*)ph;
    float* B  = (float*)pb;
    float* WP = (float*)pw;

    const int NT = 256;
    const int node_blocks  = (N_NODES + NT - 1) / NT;        // 391
    const int edge2_blocks = (N_EDGES / 2 + NT - 1) / NT;    // 2 edges/thread
    const int gemm_blocks  = N_NODES / 32;                   // 3125
    const int gath_blocks  = N_NODES / 8;                    // warp/node, 8/block
    const int pack_blocks  = (2 * D * D + NT - 1) / NT;      // 128

    // CSR build + bookkeeping (graph-capturable, deterministic)
    zb_kernel<<<node_blocks, NT>>>(batch);
    hist_kernel<<<edge2_blocks, NT>>>(ei + N_EDGES);
    blockred_kernel<<<node_blocks, NT>>>();
    bscan_kernel<<<1, 512>>>();
    blockscan_kernel<<<node_blocks, NT>>>();
    place_kernel<<<edge2_blocks, NT>>>(ei);
    pack2_kernel<<<pack_blocks, NT>>>(W0, W1, WP);

    // layer 0: A0 = agg(x); Y0 = relu(A0 W0 + b0)
    gather_kernel<<<gath_blocks, NT>>>(x, H);
    gemm_br_kernel<<<gemm_blocks, NT>>>(H, WP + 0 * D * D, b0, B);

    // layer 1: A1 = agg(Y0); Y1 = relu(A1 W1 + b1)
    gather_kernel<<<gath_blocks, NT>>>(B, H);
    gemm_br_kernel<<<gemm_blocks, NT>>>(H, WP + 1 * D * D, b1, B);

    // layer 2 (projection folded into head): S = pool(agg(Y1))
    gather_pool_kernel<<<gath_blocks, NT>>>(B, batch);

    head_kernel<<<N_GRAPHS, D>>>(W2, b2, lW, lb, out);
}

// round 13
// speedup vs baseline: 1.4778x; 1.4778x over previous
#include <cuda_runtime.h>
#include <math.h>

#define N_NODES   100000
#define N_EDGES   1600000
#define D         128
#define N_GRAPHS  128
#define N_CLASSES 10

typedef unsigned long long ull;

// packed dual-FMA: acc(2xf32) += a(2xf32) * b(2xf32)
#define FMA2(acc, a, b) \
    asm("fma.rn.f32x2 %0, %1, %2, %0;" : "+l"(acc) : "l"(a), "l"(b))

// ---------------- scratch (static device globals; no allocs) ----------------
__device__ __align__(16) float g_h  [(size_t)N_NODES * D];   // ping buffer
__device__ __align__(16) float g_buf[(size_t)N_NODES * D];   // pong buffer
__device__ __align__(16) float g_wp [2][D * D];              // k-pair-packed W0,W1
__device__ float g_dinv[N_NODES];
__device__ int   g_degi[N_NODES];
__device__ int   g_off [N_NODES + 1];
__device__ int   g_cur [N_NODES];
__device__ __align__(8) int2 g_csr[N_EDGES];                 // {src, norm bits}
__device__ __align__(16) float g_sums[N_GRAPHS * D];
__device__ int   g_end [N_GRAPHS];
__device__ int   g_bsum[391];
__device__ int   g_bpre[391];

// ---------------- setup: zero + graph boundaries (one launch) -------------
__global__ void zb_kernel(const int* __restrict__ batch) {
    int i = blockIdx.x * blockDim.x + threadIdx.x;
    if (i < N_NODES)      g_degi[i] = 0;
    if (i < N_GRAPHS * D) g_sums[i] = 0.0f;
    if (i < N_NODES) {
        int b  = batch[i];
        int bn = (i + 1 < N_NODES) ? batch[i + 1] : N_GRAPHS;
        for (int g = b; g < bn; g++) g_end[g] = i + 1;
        if (i == 0)
            for (int g = 0; g < b; g++) g_end[g] = 0;
    }
}

__global__ void hist_kernel(const int* __restrict__ dst) {
    int e = blockIdx.x * blockDim.x + threadIdx.x;
    if (e < N_EDGES) atomicAdd(&g_degi[dst[e]], 1);
}

// ---- 3-phase parallel scan over g_degi -> g_off / g_cur (+dinv fold) ----
__global__ void blockred_kernel() {           // grid 391 x 256
    __shared__ int sh[256];
    int t = threadIdx.x;
    int i = blockIdx.x * 256 + t;
    sh[t] = (i < N_NODES) ? g_degi[i] : 0;
    __syncthreads();
    for (int ofs = 128; ofs > 0; ofs >>= 1) {
        if (t < ofs) sh[t] += sh[t + ofs];
        __syncthreads();
    }
    if (t == 0) g_bsum[blockIdx.x] = sh[0];
}

__global__ void bscan_kernel() {              // 1 block x 512
    __shared__ int sh[512];
    int t = threadIdx.x;
    int v = (t < 391) ? g_bsum[t] : 0;
    sh[t] = v;
    __syncthreads();
    for (int ofs = 1; ofs < 512; ofs <<= 1) {
        int u = (t >= ofs) ? sh[t - ofs] : 0;
        __syncthreads();
        sh[t] += u;
        __syncthreads();
    }
    if (t < 391) g_bpre[t] = sh[t] - v;       // exclusive prefix of block sums
    if (t == 0) g_off[N_NODES] = N_EDGES;
}

__global__ void blockscan_kernel() {          // grid 391 x 256; also dinv
    __shared__ int sh[256];
    int t = threadIdx.x;
    int i = blockIdx.x * 256 + t;
    int v = (i < N_NODES) ? g_degi[i] : 0;
    sh[t] = v;
    __syncthreads();
    for (int ofs = 1; ofs < 256; ofs <<= 1) {
        int u = (t >= ofs) ? sh[t - ofs] : 0;
        __syncthreads();
        sh[t] += u;
        __syncthreads();
    }
    if (i < N_NODES) {
        int excl = sh[t] - v + g_bpre[blockIdx.x];
        g_off[i] = excl;
        g_cur[i] = excl;
        g_dinv[i] = rsqrtf((float)v + 1.0f);
    }
}

__global__ void place_kernel(const int* __restrict__ ei) {
    int e = blockIdx.x * blockDim.x + threadIdx.x;
    if (e >= N_EDGES) return;
    int s = ei[e];
    int d = ei[N_EDGES + e];
    int pos = atomicAdd(&g_cur[d], 1);
    float nrm = g_dinv[s] * g_dinv[d];
    g_csr[pos] = make_int2(s, __float_as_int(nrm));
}

// ---------------- W pack (both weights, one launch) -----------------------
// WP[(k/2)*2D + c*2 + (k&1)] = W[k][c]
__global__ void pack2_kernel(const float* __restrict__ W0,
                             const float* __restrict__ W1,
                             float* __restrict__ WP) {
    int i = blockIdx.x * blockDim.x + threadIdx.x;   // over 2*D*D
    if (i >= 2 * D * D) return;
    const float* W = (i < D * D) ? W0 : W1;
    int ii = (i < D * D) ? i : i - D * D;
    int base = (i < D * D) ? 0 : D * D;
    int k = ii >> 7, c = ii & 127;
    WP[base + (k >> 1) * (2 * D) + c * 2 + (k & 1)] = W[ii];
}

// ---------------- GEMM+bias+relu: Y = relu(X @ W + b) ---------------------
__global__ void gemm_br_kernel(const float* __restrict__ X,
                               const float* __restrict__ WP,
                               const float* __restrict__ b,
                               float* __restrict__ Y) {
    int block_row = blockIdx.x * 32;
    int lane = threadIdx.x & 31;
    int rt   = threadIdx.x >> 5;

    ull acc2[4][4];
#pragma unroll
    for (int j = 0; j < 4; j++)
#pragma unroll
        for (int c = 0; c < 4; c++) acc2[j][c] = 0ULL;

    for (int k = 0; k < D; k += 4) {
        ulonglong2 w0  = *(const ulonglong2*)&WP[(k >> 1) * (2 * D) + lane * 8];
        ulonglong2 w0b = *(const ulonglong2*)&WP[(k >> 1) * (2 * D) + lane * 8 + 4];
        ulonglong2 w1  = *(const ulonglong2*)&WP[((k >> 1) + 1) * (2 * D) + lane * 8];
        ulonglong2 w1b = *(const ulonglong2*)&WP[((k >> 1) + 1) * (2 * D) + lane * 8 + 4];
#pragma unroll
        for (int j = 0; j < 4; j++) {
            int r = block_row + rt + 8 * j;
            ulonglong2 xa = *(const ulonglong2*)&X[(size_t)r * D + k];
            FMA2(acc2[j][0], xa.x, w0.x);
            FMA2(acc2[j][1], xa.x, w0.y);
            FMA2(acc2[j][2], xa.x, w0b.x);
            FMA2(acc2[j][3], xa.x, w0b.y);
            FMA2(acc2[j][0], xa.y, w1.x);
            FMA2(acc2[j][1], xa.y, w1.y);
            FMA2(acc2[j][2], xa.y, w1b.x);
            FMA2(acc2[j][3], xa.y, w1b.y);
        }
    }
    float4 bb = ((const float4*)b)[lane];
    float bv[4] = {bb.x, bb.y, bb.z, bb.w};
#pragma unroll
    for (int j = 0; j < 4; j++) {
        float o[4];
#pragma unroll
        for (int c = 0; c < 4; c++) {
            unsigned lo, hi;
            asm("mov.b64 {%0,%1}, %2;" : "=r"(lo), "=r"(hi) : "l"(acc2[j][c]));
            o[c] = fmaxf(__uint_as_float(lo) + __uint_as_float(hi) + bv[c], 0.0f);
        }
        int r = block_row + rt + 8 * j;
        *(float4*)&Y[(size_t)r * D + lane * 4] =
            make_float4(o[0], o[1], o[2], o[3]);
    }
}

// ---------------- pure gather (R11-proven body): --------------------------
// out = dinv^2*x_node + sum norm*x_src ; single accumulator, 8-wide MLP
__device__ __forceinline__ float4 f4fma(float4 a, float n, float4 v) {
    a.x += n * v.x; a.y += n * v.y; a.z += n * v.z; a.w += n * v.w;
    return a;
}

__device__ __forceinline__ float4 gather_body(const float* __restrict__ X,
                                              int node, int lane) {
    float di = g_dinv[node];
    float s  = di * di;
    float4 acc = ((const float4*)(X + (size_t)node * D))[lane];
    acc.x *= s; acc.y *= s; acc.z *= s; acc.w *= s;

    int beg = g_off[node], end = g_off[node + 1];
    int j = beg;
    for (; j + 8 <= end; j += 8) {             // 8-wide independent load chains
        int2 e0 = g_csr[j + 0], e1 = g_csr[j + 1];
        int2 e2 = g_csr[j + 2], e3 = g_csr[j + 3];
        int2 e4 = g_csr[j + 4], e5 = g_csr[j + 5];
        int2 e6 = g_csr[j + 6], e7 = g_csr[j + 7];
        float4 v0 = ((const float4*)(X + (size_t)e0.x * D))[lane];
        float4 v1 = ((const float4*)(X + (size_t)e1.x * D))[lane];
        float4 v2 = ((const float4*)(X + (size_t)e2.x * D))[lane];
        float4 v3 = ((const float4*)(X + (size_t)e3.x * D))[lane];
        float4 v4 = ((const float4*)(X + (size_t)e4.x * D))[lane];
        float4 v5 = ((const float4*)(X + (size_t)e5.x * D))[lane];
        float4 v6 = ((const float4*)(X + (size_t)e6.x * D))[lane];
        float4 v7 = ((const float4*)(X + (size_t)e7.x * D))[lane];
        acc = f4fma(acc, __int_as_float(e0.y), v0);
        acc = f4fma(acc, __int_as_float(e1.y), v1);
        acc = f4fma(acc, __int_as_float(e2.y), v2);
        acc = f4fma(acc, __int_as_float(e3.y), v3);
        acc = f4fma(acc, __int_as_float(e4.y), v4);
        acc = f4fma(acc, __int_as_float(e5.y), v5);
        acc = f4fma(acc, __int_as_float(e6.y), v6);
        acc = f4fma(acc, __int_as_float(e7.y), v7);
    }
    for (; j + 2 <= end; j += 2) {
        int2 e0 = g_csr[j + 0], e1 = g_csr[j + 1];
        float4 v0 = ((const float4*)(X + (size_t)e0.x * D))[lane];
        float4 v1 = ((const float4*)(X + (size_t)e1.x * D))[lane];
        acc = f4fma(acc, __int_as_float(e0.y), v0);
        acc = f4fma(acc, __int_as_float(e1.y), v1);
    }
    if (j < end) {
        int2 e = g_csr[j];
        float4 v = ((const float4*)(X + (size_t)e.x * D))[lane];
        acc = f4fma(acc, __int_as_float(e.y), v);
    }
    return acc;
}

__global__ void gather_kernel(const float* __restrict__ X,
                              float* __restrict__ out) {
    int node = (blockIdx.x * blockDim.x + threadIdx.x) >> 5;
    if (node >= N_NODES) return;
    int lane = threadIdx.x & 31;
    float4 acc = gather_body(X, node, lane);
    ((float4*)(out + (size_t)node * D))[lane] = acc;
}

// last layer: gather on PRE-GEMM features, pooled into g_sums (linearity:
// sum_g agg(Y W2) = (sum_g agg(Y)) W2, applied in head)
__global__ void gather_pool_kernel(const float* __restrict__ X,
                                   const int* __restrict__ batch) {
    int node = (blockIdx.x * blockDim.x + threadIdx.x) >> 5;
    if (node >= N_NODES) return;
    int lane = threadIdx.x & 31;
    float4 acc = gather_body(X, node, lane);
    int g = batch[node];
    float* p = &g_sums[g * D + lane * 4];
    atomicAdd(p + 0, acc.x);
    atomicAdd(p + 1, acc.y);
    atomicAdd(p + 2, acc.z);
    atomicAdd(p + 3, acc.w);
}

// ---------------- head: S·W2/cnt + b2 -> linear -> softmax ----------------
__global__ void head_kernel(const float* __restrict__ W2,
                            const float* __restrict__ b2,
                            const float* __restrict__ lin_W,
                            const float* __restrict__ lin_b,
                            float* __restrict__ out) {
    __shared__ float sp[D];
    __shared__ float sl[N_CLASSES];
    int g = blockIdx.x;
    int c = threadIdx.x;
    int cnt = g_end[g] - (g > 0 ? g_end[g - 1] : 0);
    float inv = 1.0f / fmaxf((float)cnt, 1.0f);

    float acc = 0.0f;
    for (int k = 0; k < D; k++)
        acc += g_sums[g * D + k] * W2[k * D + c];
    sp[c] = acc * inv + b2[c];
    __syncthreads();

    if (c < N_CLASSES) {
        float l = lin_b[c];
        for (int k = 0; k < D; k++)
            l += sp[k] * lin_W[k * N_CLASSES + c];
        sl[c] = l;
    }
    __syncthreads();

    if (c == 0) {
        float m = sl[0];
#pragma unroll
        for (int j = 1; j < N_CLASSES; j++) m = fmaxf(m, sl[j]);
        float e[N_CLASSES], ssum = 0.0f;
#pragma unroll
        for (int j = 0; j < N_CLASSES; j++) { e[j] = expf(sl[j] - m); ssum += e[j]; }
        float isum = 1.0f / ssum;
#pragma unroll
        for (int j = 0; j < N_CLASSES; j++)
            out[g * N_CLASSES + j] = e[j] * isum;
    }
}

// ---------------- launch ----------------
extern "C" void kernel_launch(void* const* d_in, const int* in_sizes, int n_in,
                              void* d_out, int out_size) {
    const float* x     = (const float*)d_in[0];
    const int*   ei    = (const int*)d_in[1];    // int32 (JAX x64 disabled)
    const int*   batch = (const int*)d_in[2];
    const float* W0    = (const float*)d_in[3];
    const float* b0    = (const float*)d_in[4];
    const float* W1    = (const float*)d_in[5];
    const float* b1    = (const float*)d_in[6];
    const float* W2    = (const float*)d_in[7];
    const float* b2    = (const float*)d_in[8];
    const float* lW    = (const float*)d_in[9];
    const float* lb    = (const float*)d_in[10];
    float* out = (float*)d_out;

    void *ph, *pb, *pw;
    cudaGetSymbolAddress(&ph, g_h);
    cudaGetSymbolAddress(&pb, g_buf);
    cudaGetSymbolAddress(&pw, g_wp);
    float* H  = (float*)ph;
    float* B  = (float*)pb;
    float* WP = (float*)pw;

    const int NT = 256;
    const int node_blocks = (N_NODES + NT - 1) / NT;   // 391
    const int edge_blocks = (N_EDGES + NT - 1) / NT;
    const int gemm_blocks = N_NODES / 32;              // 3125
    const int gath_blocks = N_NODES / 8;               // warp/node, 8/block
    const int pack_blocks = (2 * D * D + NT - 1) / NT; // 128

    // CSR build + bookkeeping (graph-capturable, deterministic)
    zb_kernel<<<node_blocks, NT>>>(batch);
    hist_kernel<<<edge_blocks, NT>>>(ei + N_EDGES);
    blockred_kernel<<<node_blocks, NT>>>();
    bscan_kernel<<<1, 512>>>();
    blockscan_kernel<<<node_blocks, NT>>>();
    place_kernel<<<edge_blocks, NT>>>(ei);
    pack2_kernel<<<pack_blocks, NT>>>(W0, W1, WP);

    // layer 0: A0 = agg(x); Y0 = relu(A0 W0 + b0)
    gather_kernel<<<gath_blocks, NT>>>(x, H);
    gemm_br_kernel<<<gemm_blocks, NT>>>(H, WP + 0 * D * D, b0, B);

    // layer 1: A1 = agg(Y0); Y1 = relu(A1 W1 + b1)
    gather_kernel<<<gath_blocks, NT>>>(B, H);
    gemm_br_kernel<<<gemm_blocks, NT>>>(H, WP + 1 * D * D, b1, B);

    // layer 2 (projection folded into head): S = pool(agg(Y1))
    gather_pool_kernel<<<gath_blocks, NT>>>(B, batch);

    head_kernel<<<N_GRAPHS, D>>>(W2, b2, lW, lb, out);
}

// round 14
// speedup vs baseline: 1.5643x; 1.0586x over previous
#include <cuda_runtime.h>
#include <cuda_bf16.h>
#include <math.h>

#define N_NODES   100000
#define N_EDGES   1600000
#define D         128
#define N_GRAPHS  128
#define N_CLASSES 10

typedef unsigned long long ull;

// packed dual-FMA: acc(2xf32) += a(2xf32) * b(2xf32)
#define FMA2(acc, a, b) \
    asm("fma.rn.f32x2 %0, %1, %2, %0;" : "+l"(acc) : "l"(a), "l"(b))

// ---------------- scratch (static device globals; no allocs) ----------------
__device__ __align__(16) float          g_h [(size_t)N_NODES * D];  // fp32 agg (GEMM in)
__device__ __align__(16) __nv_bfloat16  g_hb[(size_t)N_NODES * D];  // bf16 features (gather in)
__device__ __align__(16) float g_wp [2][D * D];              // k-pair-packed W0,W1
__device__ float g_dinv[N_NODES];
__device__ int   g_degi[N_NODES];
__device__ int   g_off [N_NODES + 1];
__device__ int   g_cur [N_NODES];
__device__ __align__(8) int2 g_csr[N_EDGES];                 // {src, norm bits}
__device__ __align__(16) float g_sums[N_GRAPHS * D];
__device__ int   g_end [N_GRAPHS];
__device__ int   g_bsum[391];
__device__ int   g_bpre[391];

// ---------------- setup: zero + graph boundaries (one launch) -------------
__global__ void zb_kernel(const int* __restrict__ batch) {
    int i = blockIdx.x * blockDim.x + threadIdx.x;
    if (i < N_NODES)      g_degi[i] = 0;
    if (i < N_GRAPHS * D) g_sums[i] = 0.0f;
    if (i < N_NODES) {
        int b  = batch[i];
        int bn = (i + 1 < N_NODES) ? batch[i + 1] : N_GRAPHS;
        for (int g = b; g < bn; g++) g_end[g] = i + 1;
        if (i == 0)
            for (int g = 0; g < b; g++) g_end[g] = 0;
    }
}

__global__ void hist_kernel(const int* __restrict__ dst) {
    int e = blockIdx.x * blockDim.x + threadIdx.x;
    if (e < N_EDGES) atomicAdd(&g_degi[dst[e]], 1);
}

// ---- 3-phase parallel scan over g_degi -> g_off / g_cur (+dinv fold) ----
__global__ void blockred_kernel() {           // grid 391 x 256
    __shared__ int sh[256];
    int t = threadIdx.x;
    int i = blockIdx.x * 256 + t;
    sh[t] = (i < N_NODES) ? g_degi[i] : 0;
    __syncthreads();
    for (int ofs = 128; ofs > 0; ofs >>= 1) {
        if (t < ofs) sh[t] += sh[t + ofs];
        __syncthreads();
    }
    if (t == 0) g_bsum[blockIdx.x] = sh[0];
}

__global__ void bscan_kernel() {              // 1 block x 512
    __shared__ int sh[512];
    int t = threadIdx.x;
    int v = (t < 391) ? g_bsum[t] : 0;
    sh[t] = v;
    __syncthreads();
    for (int ofs = 1; ofs < 512; ofs <<= 1) {
        int u = (t >= ofs) ? sh[t - ofs] : 0;
        __syncthreads();
        sh[t] += u;
        __syncthreads();
    }
    if (t < 391) g_bpre[t] = sh[t] - v;       // exclusive prefix of block sums
    if (t == 0) g_off[N_NODES] = N_EDGES;
}

__global__ void blockscan_kernel() {          // grid 391 x 256; also dinv
    __shared__ int sh[256];
    int t = threadIdx.x;
    int i = blockIdx.x * 256 + t;
    int v = (i < N_NODES) ? g_degi[i] : 0;
    sh[t] = v;
    __syncthreads();
    for (int ofs = 1; ofs < 256; ofs <<= 1) {
        int u = (t >= ofs) ? sh[t - ofs] : 0;
        __syncthreads();
        sh[t] += u;
        __syncthreads();
    }
    if (i < N_NODES) {
        int excl = sh[t] - v + g_bpre[blockIdx.x];
        g_off[i] = excl;
        g_cur[i] = excl;
        g_dinv[i] = rsqrtf((float)v + 1.0f);
    }
}

__global__ void place_kernel(const int* __restrict__ ei) {
    int e = blockIdx.x * blockDim.x + threadIdx.x;
    if (e >= N_EDGES) return;
    int s = ei[e];
    int d = ei[N_EDGES + e];
    int pos = atomicAdd(&g_cur[d], 1);
    float nrm = g_dinv[s] * g_dinv[d];
    g_csr[pos] = make_int2(s, __float_as_int(nrm));
}

// ---------------- W pack (both weights, one launch) -----------------------
// WP[(k/2)*2D + c*2 + (k&1)] = W[k][c]
__global__ void pack2_kernel(const float* __restrict__ W0,
                             const float* __restrict__ W1,
                             float* __restrict__ WP) {
    int i = blockIdx.x * blockDim.x + threadIdx.x;   // over 2*D*D
    if (i >= 2 * D * D) return;
    const float* W = (i < D * D) ? W0 : W1;
    int ii = (i < D * D) ? i : i - D * D;
    int base = (i < D * D) ? 0 : D * D;
    int k = ii >> 7, c = ii & 127;
    WP[base + (k >> 1) * (2 * D) + c * 2 + (k & 1)] = W[ii];
}

// ---------------- fp32 -> bf16 convert (x into g_hb) ----------------------
__global__ void cvt_kernel(const float* __restrict__ X,
                           __nv_bfloat16* __restrict__ Xb) {
    int idx = blockIdx.x * blockDim.x + threadIdx.x;   // over N*32 float4s
    if (idx >= N_NODES * 32) return;
    float4 v = ((const float4*)X)[idx];
    __nv_bfloat162 lo = __float22bfloat162_rn(make_float2(v.x, v.y));
    __nv_bfloat162 hi = __float22bfloat162_rn(make_float2(v.z, v.w));
    uint2 u;
    u.x = *reinterpret_cast<unsigned*>(&lo);
    u.y = *reinterpret_cast<unsigned*>(&hi);
    ((uint2*)Xb)[idx] = u;
}

// ---------------- GEMM+bias+relu: Yb = bf16(relu(X @ W + b)) --------------
__global__ void gemm_br_kernel(const float* __restrict__ X,
                               const float* __restrict__ WP,
                               const float* __restrict__ b,
                               __nv_bfloat16* __restrict__ Yb) {
    int block_row = blockIdx.x * 32;
    int lane = threadIdx.x & 31;
    int rt   = threadIdx.x >> 5;

    ull acc2[4][4];
#pragma unroll
    for (int j = 0; j < 4; j++)
#pragma unroll
        for (int c = 0; c < 4; c++) acc2[j][c] = 0ULL;

    for (int k = 0; k < D; k += 4) {
        ulonglong2 w0  = *(const ulonglong2*)&WP[(k >> 1) * (2 * D) + lane * 8];
        ulonglong2 w0b = *(const ulonglong2*)&WP[(k >> 1) * (2 * D) + lane * 8 + 4];
        ulonglong2 w1  = *(const ulonglong2*)&WP[((k >> 1) + 1) * (2 * D) + lane * 8];
        ulonglong2 w1b = *(const ulonglong2*)&WP[((k >> 1) + 1) * (2 * D) + lane * 8 + 4];
#pragma unroll
        for (int j = 0; j < 4; j++) {
            int r = block_row + rt + 8 * j;
            ulonglong2 xa = *(const ulonglong2*)&X[(size_t)r * D + k];
            FMA2(acc2[j][0], xa.x, w0.x);
            FMA2(acc2[j][1], xa.x, w0.y);
            FMA2(acc2[j][2], xa.x, w0b.x);
            FMA2(acc2[j][3], xa.x, w0b.y);
            FMA2(acc2[j][0], xa.y, w1.x);
            FMA2(acc2[j][1], xa.y, w1.y);
            FMA2(acc2[j][2], xa.y, w1b.x);
            FMA2(acc2[j][3], xa.y, w1b.y);
        }
    }
    float4 bb = ((const float4*)b)[lane];
    float bv[4] = {bb.x, bb.y, bb.z, bb.w};
#pragma unroll
    for (int j = 0; j < 4; j++) {
        float o[4];
#pragma unroll
        for (int c = 0; c < 4; c++) {
            unsigned lo, hi;
            asm("mov.b64 {%0,%1}, %2;" : "=r"(lo), "=r"(hi) : "l"(acc2[j][c]));
            o[c] = fmaxf(__uint_as_float(lo) + __uint_as_float(hi) + bv[c], 0.0f);
        }
        int r = block_row + rt + 8 * j;
        __nv_bfloat162 p0 = __float22bfloat162_rn(make_float2(o[0], o[1]));
        __nv_bfloat162 p1 = __float22bfloat162_rn(make_float2(o[2], o[3]));
        uint2 u;
        u.x = *reinterpret_cast<unsigned*>(&p0);
        u.y = *reinterpret_cast<unsigned*>(&p1);
        ((uint2*)(Yb + (size_t)r * D))[lane] = u;
    }
}

// ---------------- pure gather (bf16 features, fp32 accumulate) ------------
__device__ __forceinline__ float4 f4fma(float4 a, float n, float4 v) {
    a.x += n * v.x; a.y += n * v.y; a.z += n * v.z; a.w += n * v.w;
    return a;
}

__device__ __forceinline__ float4 bf4(uint2 u) {
    __nv_bfloat162 b0 = *reinterpret_cast<__nv_bfloat162*>(&u.x);
    __nv_bfloat162 b1 = *reinterpret_cast<__nv_bfloat162*>(&u.y);
    float2 f0 = __bfloat1622float2(b0);
    float2 f1 = __bfloat1622float2(b1);
    return make_float4(f0.x, f0.y, f1.x, f1.y);
}

__device__ __forceinline__ float4 gather_body(const __nv_bfloat16* __restrict__ Xb,
                                              int node, int lane) {
    float di = g_dinv[node];
    float s  = di * di;
    float4 acc = bf4(((const uint2*)(Xb + (size_t)node * D))[lane]);
    acc.x *= s; acc.y *= s; acc.z *= s; acc.w *= s;

    int beg = g_off[node], end = g_off[node + 1];
    int j = beg;
    for (; j + 8 <= end; j += 8) {             // 8-wide independent load chains
        int2 e0 = g_csr[j + 0], e1 = g_csr[j + 1];
        int2 e2 = g_csr[j + 2], e3 = g_csr[j + 3];
        int2 e4 = g_csr[j + 4], e5 = g_csr[j + 5];
        int2 e6 = g_csr[j + 6], e7 = g_csr[j + 7];
        uint2 u0 = ((const uint2*)(Xb + (size_t)e0.x * D))[lane];
        uint2 u1 = ((const uint2*)(Xb + (size_t)e1.x * D))[lane];
        uint2 u2 = ((const uint2*)(Xb + (size_t)e2.x * D))[lane];
        uint2 u3 = ((const uint2*)(Xb + (size_t)e3.x * D))[lane];
        uint2 u4 = ((const uint2*)(Xb + (size_t)e4.x * D))[lane];
        uint2 u5 = ((const uint2*)(Xb + (size_t)e5.x * D))[lane];
        uint2 u6 = ((const uint2*)(Xb + (size_t)e6.x * D))[lane];
        uint2 u7 = ((const uint2*)(Xb + (size_t)e7.x * D))[lane];
        acc = f4fma(acc, __int_as_float(e0.y), bf4(u0));
        acc = f4fma(acc, __int_as_float(e1.y), bf4(u1));
        acc = f4fma(acc, __int_as_float(e2.y), bf4(u2));
        acc = f4fma(acc, __int_as_float(e3.y), bf4(u3));
        acc = f4fma(acc, __int_as_float(e4.y), bf4(u4));
        acc = f4fma(acc, __int_as_float(e5.y), bf4(u5));
        acc = f4fma(acc, __int_as_float(e6.y), bf4(u6));
        acc = f4fma(acc, __int_as_float(e7.y), bf4(u7));
    }
    for (; j + 2 <= end; j += 2) {
        int2 e0 = g_csr[j + 0], e1 = g_csr[j + 1];
        uint2 u0 = ((const uint2*)(Xb + (size_t)e0.x * D))[lane];
        uint2 u1 = ((const uint2*)(Xb + (size_t)e1.x * D))[lane];
        acc = f4fma(acc, __int_as_float(e0.y), bf4(u0));
        acc = f4fma(acc, __int_as_float(e1.y), bf4(u1));
    }
    if (j < end) {
        int2 e = g_csr[j];
        uint2 u = ((const uint2*)(Xb + (size_t)e.x * D))[lane];
        acc = f4fma(acc, __int_as_float(e.y), bf4(u));
    }
    return acc;
}

__global__ void gather_kernel(const __nv_bfloat16* __restrict__ Xb,
                              float* __restrict__ out) {
    int node = (blockIdx.x * blockDim.x + threadIdx.x) >> 5;
    if (node >= N_NODES) return;
    int lane = threadIdx.x & 31;
    float4 acc = gather_body(Xb, node, lane);
    ((float4*)(out + (size_t)node * D))[lane] = acc;
}

// last layer: gather on PRE-GEMM bf16 features, pooled into g_sums (linearity)
__global__ void gather_pool_kernel(const __nv_bfloat16* __restrict__ Xb,
                                   const int* __restrict__ batch) {
    int node = (blockIdx.x * blockDim.x + threadIdx.x) >> 5;
    if (node >= N_NODES) return;
    int lane = threadIdx.x & 31;
    float4 acc = gather_body(Xb, node, lane);
    int g = batch[node];
    float* p = &g_sums[g * D + lane * 4];
    atomicAdd(p + 0, acc.x);
    atomicAdd(p + 1, acc.y);
    atomicAdd(p + 2, acc.z);
    atomicAdd(p + 3, acc.w);
}

// ---------------- head: S·W2/cnt + b2 -> linear -> softmax ----------------
__global__ void head_kernel(const float* __restrict__ W2,
                            const float* __restrict__ b2,
                            const float* __restrict__ lin_W,
                            const float* __restrict__ lin_b,
                            float* __restrict__ out) {
    __shared__ float sp[D];
    __shared__ float sl[N_CLASSES];
    int g = blockIdx.x;
    int c = threadIdx.x;
    int cnt = g_end[g] - (g > 0 ? g_end[g - 1] : 0);
    float inv = 1.0f / fmaxf((float)cnt, 1.0f);

    float acc = 0.0f;
    for (int k = 0; k < D; k++)
        acc += g_sums[g * D + k] * W2[k * D + c];
    sp[c] = acc * inv + b2[c];
    __syncthreads();

    if (c < N_CLASSES) {
        float l = lin_b[c];
        for (int k = 0; k < D; k++)
            l += sp[k] * lin_W[k * N_CLASSES + c];
        sl[c] = l;
    }
    __syncthreads();

    if (c == 0) {
        float m = sl[0];
#pragma unroll
        for (int j = 1; j < N_CLASSES; j++) m = fmaxf(m, sl[j]);
        float e[N_CLASSES], ssum = 0.0f;
#pragma unroll
        for (int j = 0; j < N_CLASSES; j++) { e[j] = expf(sl[j] - m); ssum += e[j]; }
        float isum = 1.0f / ssum;
#pragma unroll
        for (int j = 0; j < N_CLASSES; j++)
            out[g * N_CLASSES + j] = e[j] * isum;
    }
}

// ---------------- launch ----------------
extern "C" void kernel_launch(void* const* d_in, const int* in_sizes, int n_in,
                              void* d_out, int out_size) {
    const float* x     = (const float*)d_in[0];
    const int*   ei    = (const int*)d_in[1];    // int32 (JAX x64 disabled)
    const int*   batch = (const int*)d_in[2];
    const float* W0    = (const float*)d_in[3];
    const float* b0    = (const float*)d_in[4];
    const float* W1    = (const float*)d_in[5];
    const float* b1    = (const float*)d_in[6];
    const float* W2    = (const float*)d_in[7];
    const float* b2    = (const float*)d_in[8];
    const float* lW    = (const float*)d_in[9];
    const float* lb    = (const float*)d_in[10];
    float* out = (float*)d_out;

    void *ph, *phb, *pw;
    cudaGetSymbolAddress(&ph,  g_h);
    cudaGetSymbolAddress(&phb, g_hb);
    cudaGetSymbolAddress(&pw,  g_wp);
    float*         A  = (float*)ph;            // fp32 agg (GEMM input)
    __nv_bfloat16* Fb = (__nv_bfloat16*)phb;   // bf16 features (gather input)
    float*         WP = (float*)pw;

    const int NT = 256;
    const int node_blocks = (N_NODES + NT - 1) / NT;   // 391
    const int edge_blocks = (N_EDGES + NT - 1) / NT;
    const int gemm_blocks = N_NODES / 32;              // 3125
    const int gath_blocks = N_NODES / 8;               // warp/node, 8/block
    const int elem_blocks = (N_NODES * 32 + NT - 1) / NT;
    const int pack_blocks = (2 * D * D + NT - 1) / NT; // 128

    // CSR build + bookkeeping (graph-capturable, deterministic)
    zb_kernel<<<node_blocks, NT>>>(batch);
    hist_kernel<<<edge_blocks, NT>>>(ei + N_EDGES);
    blockred_kernel<<<node_blocks, NT>>>();
    bscan_kernel<<<1, 512>>>();
    blockscan_kernel<<<node_blocks, NT>>>();
    place_kernel<<<edge_blocks, NT>>>(ei);
    pack2_kernel<<<pack_blocks, NT>>>(W0, W1, WP);
    cvt_kernel<<<elem_blocks, NT>>>(x, Fb);            // x -> bf16

    // layer 0: A0 = agg(xb); Y0b = bf16(relu(A0 W0 + b0))
    gather_kernel<<<gath_blocks, NT>>>(Fb, A);
    gemm_br_kernel<<<gemm_blocks, NT>>>(A, WP + 0 * D * D, b0, Fb);

    // layer 1: A1 = agg(Y0b); Y1b = bf16(relu(A1 W1 + b1))
    gather_kernel<<<gath_blocks, NT>>>(Fb, A);
    gemm_br_kernel<<<gemm_blocks, NT>>>(A, WP + 1 * D * D, b1, Fb);

    // layer 2 (projection folded into head): S = pool(agg(Y1b))
    gather_pool_kernel<<<gath_blocks, NT>>>(Fb, batch);

    head_kernel<<<N_GRAPHS, D>>>(W2, b2, lW, lb, out);
}

// round 15
// speedup vs baseline: 2.3111x; 1.4774x over previous
#include <cuda_runtime.h>
#include <cuda_bf16.h>
#include <math.h>

#define N_NODES   100000
#define N_EDGES   1600000
#define D         128
#define N_GRAPHS  128
#define N_CLASSES 10

typedef unsigned long long ull;

// packed dual-FMA: acc(2xf32) += a(2xf32) * b(2xf32)
#define FMA2(acc, a, b) \
    asm("fma.rn.f32x2 %0, %1, %2, %0;" : "+l"(acc) : "l"(a), "l"(b))

// ---------------- scratch (static device globals; no allocs) ----------------
__device__ __align__(16) float          g_h [(size_t)N_NODES * D];  // fp32 agg (GEMM in)
__device__ __align__(16) __nv_bfloat16  g_hb[(size_t)N_NODES * D];  // bf16 features (gather in)
__device__ __align__(16) float g_wp [2][D * D];              // k-pair-packed W0,W1
__device__ float g_dinv[N_NODES];
__device__ int   g_degi[N_NODES];
__device__ int   g_off [N_NODES + 1];
__device__ int   g_cur [N_NODES];
__device__ __align__(8) int2 g_csr[N_EDGES];                 // {src, norm bits}
__device__ __align__(16) float g_sums[N_GRAPHS * D];
__device__ int   g_end [N_GRAPHS];
__device__ int   g_bsum[391];
__device__ int   g_bpre[391];

// ---------------- setup: zero + graph boundaries (one launch) -------------
__global__ void zb_kernel(const int* __restrict__ batch) {
    int i = blockIdx.x * blockDim.x + threadIdx.x;
    if (i < N_NODES)      g_degi[i] = 0;
    if (i < N_GRAPHS * D) g_sums[i] = 0.0f;
    if (i < N_NODES) {
        int b  = batch[i];
        int bn = (i + 1 < N_NODES) ? batch[i + 1] : N_GRAPHS;
        for (int g = b; g < bn; g++) g_end[g] = i + 1;
        if (i == 0)
            for (int g = 0; g < b; g++) g_end[g] = 0;
    }
}

__global__ void hist_kernel(const int* __restrict__ dst) {
    int e = blockIdx.x * blockDim.x + threadIdx.x;
    if (e < N_EDGES) atomicAdd(&g_degi[dst[e]], 1);
}

// ---- 3-phase parallel scan over g_degi -> g_off / g_cur (+dinv fold) ----
__global__ void blockred_kernel() {           // grid 391 x 256
    __shared__ int sh[256];
    int t = threadIdx.x;
    int i = blockIdx.x * 256 + t;
    sh[t] = (i < N_NODES) ? g_degi[i] : 0;
    __syncthreads();
    for (int ofs = 128; ofs > 0; ofs >>= 1) {
        if (t < ofs) sh[t] += sh[t + ofs];
        __syncthreads();
    }
    if (t == 0) g_bsum[blockIdx.x] = sh[0];
}

__global__ void bscan_kernel() {              // 1 block x 512
    __shared__ int sh[512];
    int t = threadIdx.x;
    int v = (t < 391) ? g_bsum[t] : 0;
    sh[t] = v;
    __syncthreads();
    for (int ofs = 1; ofs < 512; ofs <<= 1) {
        int u = (t >= ofs) ? sh[t - ofs] : 0;
        __syncthreads();
        sh[t] += u;
        __syncthreads();
    }
    if (t < 391) g_bpre[t] = sh[t] - v;       // exclusive prefix of block sums
    if (t == 0) g_off[N_NODES] = N_EDGES;
}

__global__ void blockscan_kernel() {          // grid 391 x 256; also dinv
    __shared__ int sh[256];
    int t = threadIdx.x;
    int i = blockIdx.x * 256 + t;
    int v = (i < N_NODES) ? g_degi[i] : 0;
    sh[t] = v;
    __syncthreads();
    for (int ofs = 1; ofs < 256; ofs <<= 1) {
        int u = (t >= ofs) ? sh[t - ofs] : 0;
        __syncthreads();
        sh[t] += u;
        __syncthreads();
    }
    if (i < N_NODES) {
        int excl = sh[t] - v + g_bpre[blockIdx.x];
        g_off[i] = excl;
        g_cur[i] = excl;
        g_dinv[i] = rsqrtf((float)v + 1.0f);
    }
}

__global__ void place_kernel(const int* __restrict__ ei) {
    int e = blockIdx.x * blockDim.x + threadIdx.x;
    if (e >= N_EDGES) return;
    int s = ei[e];
    int d = ei[N_EDGES + e];
    int pos = atomicAdd(&g_cur[d], 1);
    float nrm = g_dinv[s] * g_dinv[d];
    g_csr[pos] = make_int2(s, __float_as_int(nrm));
}

// ---------------- W pack (both weights, one launch) -----------------------
// WP[(k/2)*2D + c*2 + (k&1)] = W[k][c]
__global__ void pack2_kernel(const float* __restrict__ W0,
                             const float* __restrict__ W1,
                             float* __restrict__ WP) {
    int i = blockIdx.x * blockDim.x + threadIdx.x;   // over 2*D*D
    if (i >= 2 * D * D) return;
    const float* W = (i < D * D) ? W0 : W1;
    int ii = (i < D * D) ? i : i - D * D;
    int base = (i < D * D) ? 0 : D * D;
    int k = ii >> 7, c = ii & 127;
    WP[base + (k >> 1) * (2 * D) + c * 2 + (k & 1)] = W[ii];
}

// ---------------- fp32 -> bf16 convert (x into g_hb) ----------------------
__global__ void cvt_kernel(const float* __restrict__ X,
                           __nv_bfloat16* __restrict__ Xb) {
    int idx = blockIdx.x * blockDim.x + threadIdx.x;   // over N*32 float4s
    if (idx >= N_NODES * 32) return;
    float4 v = ((const float4*)X)[idx];
    __nv_bfloat162 lo = __float22bfloat162_rn(make_float2(v.x, v.y));
    __nv_bfloat162 hi = __float22bfloat162_rn(make_float2(v.z, v.w));
    uint2 u;
    u.x = *reinterpret_cast<unsigned*>(&lo);
    u.y = *reinterpret_cast<unsigned*>(&hi);
    ((uint2*)Xb)[idx] = u;
}

// ---------------- GEMM+bias+relu: Yb = bf16(relu(X @ W + b)) --------------
__global__ void gemm_br_kernel(const float* __restrict__ X,
                               const float* __restrict__ WP,
                               const float* __restrict__ b,
                               __nv_bfloat16* __restrict__ Yb) {
    int block_row = blockIdx.x * 32;
    int lane = threadIdx.x & 31;
    int rt   = threadIdx.x >> 5;

    ull acc2[4][4];
#pragma unroll
    for (int j = 0; j < 4; j++)
#pragma unroll
        for (int c = 0; c < 4; c++) acc2[j][c] = 0ULL;

    for (int k = 0; k < D; k += 4) {
        ulonglong2 w0  = *(const ulonglong2*)&WP[(k >> 1) * (2 * D) + lane * 8];
        ulonglong2 w0b = *(const ulonglong2*)&WP[(k >> 1) * (2 * D) + lane * 8 + 4];
        ulonglong2 w1  = *(const ulonglong2*)&WP[((k >> 1) + 1) * (2 * D) + lane * 8];
        ulonglong2 w1b = *(const ulonglong2*)&WP[((k >> 1) + 1) * (2 * D) + lane * 8 + 4];
#pragma unroll
        for (int j = 0; j < 4; j++) {
            int r = block_row + rt + 8 * j;
            ulonglong2 xa = *(const ulonglong2*)&X[(size_t)r * D + k];
            FMA2(acc2[j][0], xa.x, w0.x);
            FMA2(acc2[j][1], xa.x, w0.y);
            FMA2(acc2[j][2], xa.x, w0b.x);
            FMA2(acc2[j][3], xa.x, w0b.y);
            FMA2(acc2[j][0], xa.y, w1.x);
            FMA2(acc2[j][1], xa.y, w1.y);
            FMA2(acc2[j][2], xa.y, w1b.x);
            FMA2(acc2[j][3], xa.y, w1b.y);
        }
    }
    float4 bb = ((const float4*)b)[lane];
    float bv[4] = {bb.x, bb.y, bb.z, bb.w};
#pragma unroll
    for (int j = 0; j < 4; j++) {
        float o[4];
#pragma unroll
        for (int c = 0; c < 4; c++) {
            unsigned lo, hi;
            asm("mov.b64 {%0,%1}, %2;" : "=r"(lo), "=r"(hi) : "l"(acc2[j][c]));
            o[c] = fmaxf(__uint_as_float(lo) + __uint_as_float(hi) + bv[c], 0.0f);
        }
        int r = block_row + rt + 8 * j;
        __nv_bfloat162 p0 = __float22bfloat162_rn(make_float2(o[0], o[1]));
        __nv_bfloat162 p1 = __float22bfloat162_rn(make_float2(o[2], o[3]));
        uint2 u;
        u.x = *reinterpret_cast<unsigned*>(&p0);
        u.y = *reinterpret_cast<unsigned*>(&p1);
        ((uint2*)(Yb + (size_t)r * D))[lane] = u;
    }
}

// ---------------- pure gather (bf16 features, fp32 accumulate) ------------
__device__ __forceinline__ float4 f4fma(float4 a, float n, float4 v) {
    a.x += n * v.x; a.y += n * v.y; a.z += n * v.z; a.w += n * v.w;
    return a;
}

__device__ __forceinline__ float4 bf4(uint2 u) {
    __nv_bfloat162 b0 = *reinterpret_cast<__nv_bfloat162*>(&u.x);
    __nv_bfloat162 b1 = *reinterpret_cast<__nv_bfloat162*>(&u.y);
    float2 f0 = __bfloat1622float2(b0);
    float2 f1 = __bfloat1622float2(b1);
    return make_float4(f0.x, f0.y, f1.x, f1.y);
}

__device__ __forceinline__ float4 gather_body(const __nv_bfloat16* __restrict__ Xb,
                                              int node, int lane) {
    float di = g_dinv[node];
    float s  = di * di;
    float4 acc = bf4(((const uint2*)(Xb + (size_t)node * D))[lane]);
    acc.x *= s; acc.y *= s; acc.z *= s; acc.w *= s;

    int beg = g_off[node], end = g_off[node + 1];
    int j = beg;
    for (; j + 8 <= end; j += 8) {             // 8-wide independent load chains
        int2 e0 = g_csr[j + 0], e1 = g_csr[j + 1];
        int2 e2 = g_csr[j + 2], e3 = g_csr[j + 3];
        int2 e4 = g_csr[j + 4], e5 = g_csr[j + 5];
        int2 e6 = g_csr[j + 6], e7 = g_csr[j + 7];
        uint2 u0 = ((const uint2*)(Xb + (size_t)e0.x * D))[lane];
        uint2 u1 = ((const uint2*)(Xb + (size_t)e1.x * D))[lane];
        uint2 u2 = ((const uint2*)(Xb + (size_t)e2.x * D))[lane];
        uint2 u3 = ((const uint2*)(Xb + (size_t)e3.x * D))[lane];
        uint2 u4 = ((const uint2*)(Xb + (size_t)e4.x * D))[lane];
        uint2 u5 = ((const uint2*)(Xb + (size_t)e5.x * D))[lane];
        uint2 u6 = ((const uint2*)(Xb + (size_t)e6.x * D))[lane];
        uint2 u7 = ((const uint2*)(Xb + (size_t)e7.x * D))[lane];
        acc = f4fma(acc, __int_as_float(e0.y), bf4(u0));
        acc = f4fma(acc, __int_as_float(e1.y), bf4(u1));
        acc = f4fma(acc, __int_as_float(e2.y), bf4(u2));
        acc = f4fma(acc, __int_as_float(e3.y), bf4(u3));
        acc = f4fma(acc, __int_as_float(e4.y), bf4(u4));
        acc = f4fma(acc, __int_as_float(e5.y), bf4(u5));
        acc = f4fma(acc, __int_as_float(e6.y), bf4(u6));
        acc = f4fma(acc, __int_as_float(e7.y), bf4(u7));
    }
    for (; j + 2 <= end; j += 2) {
        int2 e0 = g_csr[j + 0], e1 = g_csr[j + 1];
        uint2 u0 = ((const uint2*)(Xb + (size_t)e0.x * D))[lane];
        uint2 u1 = ((const uint2*)(Xb + (size_t)e1.x * D))[lane];
        acc = f4fma(acc, __int_as_float(e0.y), bf4(u0));
        acc = f4fma(acc, __int_as_float(e1.y), bf4(u1));
    }
    if (j < end) {
        int2 e = g_csr[j];
        uint2 u = ((const uint2*)(Xb + (size_t)e.x * D))[lane];
        acc = f4fma(acc, __int_as_float(e.y), bf4(u));
    }
    return acc;
}

__global__ void gather_kernel(const __nv_bfloat16* __restrict__ Xb,
                              float* __restrict__ out) {
    int node = (blockIdx.x * blockDim.x + threadIdx.x) >> 5;
    if (node >= N_NODES) return;
    int lane = threadIdx.x & 31;
    float4 acc = gather_body(Xb, node, lane);
    ((float4*)(out + (size_t)node * D))[lane] = acc;
}

// last layer: gather + pool. Interior blocks (all 8 nodes in same graph —
// batch is sorted, ~99% of blocks) reduce through smem and issue ONE warp of
// atomics per block: 12.8M contended atomics -> ~1.7M.
__global__ void gather_pool_kernel(const __nv_bfloat16* __restrict__ Xb,
                                   const int* __restrict__ batch) {
    __shared__ float sred[8][D];               // 4 KB
    int warp = threadIdx.x >> 5;               // 0..7
    int node = blockIdx.x * 8 + warp;
    int lane = threadIdx.x & 31;
    float4 acc = gather_body(Xb, node, lane);

    int g0 = batch[blockIdx.x * 8];
    int g7 = batch[blockIdx.x * 8 + 7];
    if (g0 == g7) {                            // uniform across block
        ((float4*)sred[warp])[lane] = acc;
        __syncthreads();
        if (warp == 0) {
            float4 s = make_float4(0.f, 0.f, 0.f, 0.f);
#pragma unroll
            for (int w = 0; w < 8; w++) {
                float4 v = ((float4*)sred[w])[lane];
                s.x += v.x; s.y += v.y; s.z += v.z; s.w += v.w;
            }
            float* p = &g_sums[g0 * D + lane * 4];
            atomicAdd(p + 0, s.x);
            atomicAdd(p + 1, s.y);
            atomicAdd(p + 2, s.z);
            atomicAdd(p + 3, s.w);
        }
    } else {                                   // boundary block: per-warp path
        int g = batch[node];
        float* p = &g_sums[g * D + lane * 4];
        atomicAdd(p + 0, acc.x);
        atomicAdd(p + 1, acc.y);
        atomicAdd(p + 2, acc.z);
        atomicAdd(p + 3, acc.w);
    }
}

// ---------------- head: S·W2/cnt + b2 -> linear -> softmax ----------------
__global__ void head_kernel(const float* __restrict__ W2,
                            const float* __restrict__ b2,
                            const float* __restrict__ lin_W,
                            const float* __restrict__ lin_b,
                            float* __restrict__ out) {
    __shared__ float sp[D];
    __shared__ float sl[N_CLASSES];
    int g = blockIdx.x;
    int c = threadIdx.x;
    int cnt = g_end[g] - (g > 0 ? g_end[g - 1] : 0);
    float inv = 1.0f / fmaxf((float)cnt, 1.0f);

    float acc = 0.0f;
    for (int k = 0; k < D; k++)
        acc += g_sums[g * D + k] * W2[k * D + c];
    sp[c] = acc * inv + b2[c];
    __syncthreads();

    if (c < N_CLASSES) {
        float l = lin_b[c];
        for (int k = 0; k < D; k++)
            l += sp[k] * lin_W[k * N_CLASSES + c];
        sl[c] = l;
    }
    __syncthreads();

    if (c == 0) {
        float m = sl[0];
#pragma unroll
        for (int j = 1; j < N_CLASSES; j++) m = fmaxf(m, sl[j]);
        float e[N_CLASSES], ssum = 0.0f;
#pragma unroll
        for (int j = 0; j < N_CLASSES; j++) { e[j] = expf(sl[j] - m); ssum += e[j]; }
        float isum = 1.0f / ssum;
#pragma unroll
        for (int j = 0; j < N_CLASSES; j++)
            out[g * N_CLASSES + j] = e[j] * isum;
    }
}

// ---------------- launch ----------------
extern "C" void kernel_launch(void* const* d_in, const int* in_sizes, int n_in,
                              void* d_out, int out_size) {
    const float* x     = (const float*)d_in[0];
    const int*   ei    = (const int*)d_in[1];    // int32 (JAX x64 disabled)
    const int*   batch = (const int*)d_in[2];
    const float* W0    = (const float*)d_in[3];
    const float* b0    = (const float*)d_in[4];
    const float* W1    = (const float*)d_in[5];
    const float* b1    = (const float*)d_in[6];
    const float* W2    = (const float*)d_in[7];
    const float* b2    = (const float*)d_in[8];
    const float* lW    = (const float*)d_in[9];
    const float* lb    = (const float*)d_in[10];
    float* out = (float*)d_out;

    void *ph, *phb, *pw;
    cudaGetSymbolAddress(&ph,  g_h);
    cudaGetSymbolAddress(&phb, g_hb);
    cudaGetSymbolAddress(&pw,  g_wp);
    float*         A  = (float*)ph;            // fp32 agg (GEMM input)
    __nv_bfloat16* Fb = (__nv_bfloat16*)phb;   // bf16 features (gather input)
    float*         WP = (float*)pw;

    const int NT = 256;
    const int node_blocks = (N_NODES + NT - 1) / NT;   // 391
    const int edge_blocks = (N_EDGES + NT - 1) / NT;
    const int gemm_blocks = N_NODES / 32;              // 3125
    const int gath_blocks = N_NODES / 8;               // warp/node, 8/block
    const int elem_blocks = (N_NODES * 32 + NT - 1) / NT;
    const int pack_blocks = (2 * D * D + NT - 1) / NT; // 128

    // CSR build + bookkeeping (graph-capturable, deterministic)
    zb_kernel<<<node_blocks, NT>>>(batch);
    hist_kernel<<<edge_blocks, NT>>>(ei + N_EDGES);
    blockred_kernel<<<node_blocks, NT>>>();
    bscan_kernel<<<1, 512>>>();
    blockscan_kernel<<<node_blocks, NT>>>();
    place_kernel<<<edge_blocks, NT>>>(ei);
    pack2_kernel<<<pack_blocks, NT>>>(W0, W1, WP);
    cvt_kernel<<<elem_blocks, NT>>>(x, Fb);            // x -> bf16

    // layer 0: A0 = agg(xb); Y0b = bf16(relu(A0 W0 + b0))
    gather_kernel<<<gath_blocks, NT>>>(Fb, A);
    gemm_br_kernel<<<gemm_blocks, NT>>>(A, WP + 0 * D * D, b0, Fb);

    // layer 1: A1 = agg(Y0b); Y1b = bf16(relu(A1 W1 + b1))
    gather_kernel<<<gath_blocks, NT>>>(Fb, A);
    gemm_br_kernel<<<gemm_blocks, NT>>>(A, WP + 1 * D * D, b1, Fb);

    // layer 2 (projection folded into head): S = pool(agg(Y1b))
    gather_pool_kernel<<<gath_blocks, NT>>>(Fb, batch);

    head_kernel<<<N_GRAPHS, D>>>(W2, b2, lW, lb, out);
}

// round 16
// speedup vs baseline: 3.2069x; 1.3876x over previous
#include <cuda_runtime.h>
#include <cuda_bf16.h>
#include <math.h>

#define N_NODES   100000
#define N_PAD     100032   // 1563 * 64 (GEMM block rows), zero-init padding
#define N_EDGES   1600000
#define D         128
#define N_GRAPHS  128
#define N_CLASSES 10

// ---------------- scratch (static device globals; no allocs) ----------------
__device__ __align__(16) float          g_h [(size_t)N_PAD * D];   // fp32 agg (GEMM in)
__device__ __align__(16) __nv_bfloat16  g_hb[(size_t)N_PAD * D];   // bf16 features (gather in)
__device__ float g_dinv[N_NODES];
__device__ int   g_degi[N_NODES];
__device__ int   g_off [N_NODES + 1];
__device__ int   g_cur [N_NODES];
__device__ __align__(8) int2 g_csr[N_EDGES];                 // {src, norm bits}
__device__ __align__(16) float g_sums[N_GRAPHS * D];
__device__ int   g_end [N_GRAPHS];
__device__ int   g_bsum[391];
__device__ int   g_bpre[391];

// ---------------- setup: zero + graph boundaries (one launch) -------------
__global__ void zb_kernel(const int* __restrict__ batch) {
    int i = blockIdx.x * blockDim.x + threadIdx.x;
    if (i < N_NODES)      g_degi[i] = 0;
    if (i < N_GRAPHS * D) g_sums[i] = 0.0f;
    if (i < N_NODES) {
        int b  = batch[i];
        int bn = (i + 1 < N_NODES) ? batch[i + 1] : N_GRAPHS;
        for (int g = b; g < bn; g++) g_end[g] = i + 1;
        if (i == 0)
            for (int g = 0; g < b; g++) g_end[g] = 0;
    }
}

__global__ void hist_kernel(const int* __restrict__ dst) {
    int e = blockIdx.x * blockDim.x + threadIdx.x;
    if (e < N_EDGES) atomicAdd(&g_degi[dst[e]], 1);
}

// ---- 3-phase parallel scan over g_degi -> g_off / g_cur (+dinv fold) ----
__global__ void blockred_kernel() {           // grid 391 x 256
    __shared__ int sh[256];
    int t = threadIdx.x;
    int i = blockIdx.x * 256 + t;
    sh[t] = (i < N_NODES) ? g_degi[i] : 0;
    __syncthreads();
    for (int ofs = 128; ofs > 0; ofs >>= 1) {
        if (t < ofs) sh[t] += sh[t + ofs];
        __syncthreads();
    }
    if (t == 0) g_bsum[blockIdx.x] = sh[0];
}

__global__ void bscan_kernel() {              // 1 block x 512
    __shared__ int sh[512];
    int t = threadIdx.x;
    int v = (t < 391) ? g_bsum[t] : 0;
    sh[t] = v;
    __syncthreads();
    for (int ofs = 1; ofs < 512; ofs <<= 1) {
        int u = (t >= ofs) ? sh[t - ofs] : 0;
        __syncthreads();
        sh[t] += u;
        __syncthreads();
    }
    if (t < 391) g_bpre[t] = sh[t] - v;       // exclusive prefix of block sums
    if (t == 0) g_off[N_NODES] = N_EDGES;
}

__global__ void blockscan_kernel() {          // grid 391 x 256; also dinv
    __shared__ int sh[256];
    int t = threadIdx.x;
    int i = blockIdx.x * 256 + t;
    int v = (i < N_NODES) ? g_degi[i] : 0;
    sh[t] = v;
    __syncthreads();
    for (int ofs = 1; ofs < 256; ofs <<= 1) {
        int u = (t >= ofs) ? sh[t - ofs] : 0;
        __syncthreads();
        sh[t] += u;
        __syncthreads();
    }
    if (i < N_NODES) {
        int excl = sh[t] - v + g_bpre[blockIdx.x];
        g_off[i] = excl;
        g_cur[i] = excl;
        g_dinv[i] = rsqrtf((float)v + 1.0f);
    }
}

__global__ void place_kernel(const int* __restrict__ ei) {
    int e = blockIdx.x * blockDim.x + threadIdx.x;
    if (e >= N_EDGES) return;
    int s = ei[e];
    int d = ei[N_EDGES + e];
    int pos = atomicAdd(&g_cur[d], 1);
    float nrm = g_dinv[s] * g_dinv[d];
    g_csr[pos] = make_int2(s, __float_as_int(nrm));
}

// ---------------- fp32 -> bf16 convert (x into g_hb) ----------------------
__global__ void cvt_kernel(const float* __restrict__ X,
                           __nv_bfloat16* __restrict__ Xb) {
    int idx = blockIdx.x * blockDim.x + threadIdx.x;   // over N*32 float4s
    if (idx >= N_NODES * 32) return;
    float4 v = ((const float4*)X)[idx];
    __nv_bfloat162 lo = __float22bfloat162_rn(make_float2(v.x, v.y));
    __nv_bfloat162 hi = __float22bfloat162_rn(make_float2(v.z, v.w));
    uint2 u;
    u.x = *reinterpret_cast<unsigned*>(&lo);
    u.y = *reinterpret_cast<unsigned*>(&hi);
    ((uint2*)Xb)[idx] = u;
}

// ---------------- tensor-core GEMM: Yb = bf16(relu(A @ W + b)) ------------
// mma.sync m16n8k8 tf32, fp32 accumulate. Block: 256 thr = 8 warps covering
// 64 rows x 128 cols (warp tile 16x64). W staged to smem as tf32, row pitch
// 136 words -> B-fragment reads hit banks thr*8+grp: conflict-free.
#define SW_PITCH 136
#define SMEM_W_BYTES (D * SW_PITCH * 4)

#define MMA_TF32(d, a0, a1, a2, a3, b0, b1) \
    asm volatile("mma.sync.aligned.m16n8k8.row.col.f32.tf32.tf32.f32 " \
                 "{%0,%1,%2,%3}, {%4,%5,%6,%7}, {%8,%9}, {%0,%1,%2,%3};" \
                 : "+f"(d[0]), "+f"(d[1]), "+f"(d[2]), "+f"(d[3]) \
                 : "r"(a0), "r"(a1), "r"(a2), "r"(a3), "r"(b0), "r"(b1))

__device__ __forceinline__ unsigned tf32(float f) {
    unsigned u;
    asm("cvt.rna.tf32.f32 %0, %1;" : "=r"(u) : "f"(f));
    return u;
}

__global__ void gemm_tc_kernel(const float* __restrict__ A,
                               const float* __restrict__ W,
                               const float* __restrict__ bias,
                               __nv_bfloat16* __restrict__ Yb) {
    extern __shared__ unsigned sW[];           // [D][SW_PITCH] tf32
    int tid = threadIdx.x;
    for (int i = tid; i < D * D; i += 256) {
        int k = i >> 7, n = i & 127;
        sW[k * SW_PITCH + n] = tf32(W[i]);
    }
    __syncthreads();

    int warp = tid >> 5, lane = tid & 31;
    int row0 = blockIdx.x * 64 + (warp & 3) * 16;
    int col0 = (warp >> 2) * 64;
    int grp = lane >> 2, thr = lane & 3;       // fragment coords

    float acc[8][4];
#pragma unroll
    for (int nt = 0; nt < 8; nt++)
#pragma unroll
        for (int c = 0; c < 4; c++) acc[nt][c] = 0.0f;

    const float* Ab = A + (size_t)(row0 + grp) * D;
#pragma unroll 2
    for (int k0 = 0; k0 < D; k0 += 8) {
        unsigned a0 = tf32(Ab[k0 + thr]);
        unsigned a1 = tf32(Ab[8 * D + k0 + thr]);
        unsigned a2 = tf32(Ab[k0 + thr + 4]);
        unsigned a3 = tf32(Ab[8 * D + k0 + thr + 4]);
#pragma unroll
        for (int nt = 0; nt < 8; nt++) {
            unsigned b0 = sW[(k0 + thr) * SW_PITCH + col0 + nt * 8 + grp];
            unsigned b1 = sW[(k0 + thr + 4) * SW_PITCH + col0 + nt * 8 + grp];
            MMA_TF32(acc[nt], a0, a1, a2, a3, b0, b1);
        }
    }

    size_t r0 = row0 + grp, r1 = r0 + 8;
#pragma unroll
    for (int nt = 0; nt < 8; nt++) {
        int c = col0 + nt * 8 + 2 * thr;
        float bv0 = bias[c], bv1 = bias[c + 1];
        float y00 = fmaxf(acc[nt][0] + bv0, 0.0f);
        float y01 = fmaxf(acc[nt][1] + bv1, 0.0f);
        float y10 = fmaxf(acc[nt][2] + bv0, 0.0f);
        float y11 = fmaxf(acc[nt][3] + bv1, 0.0f);
        __nv_bfloat162 p0 = __float22bfloat162_rn(make_float2(y00, y01));
        __nv_bfloat162 p1 = __float22bfloat162_rn(make_float2(y10, y11));
        *(unsigned*)(Yb + r0 * D + c) = *reinterpret_cast<unsigned*>(&p0);
        *(unsigned*)(Yb + r1 * D + c) = *reinterpret_cast<unsigned*>(&p1);
    }
}

// ---------------- pure gather (bf16 features, fp32 accumulate) ------------
__device__ __forceinline__ float4 f4fma(float4 a, float n, float4 v) {
    a.x += n * v.x; a.y += n * v.y; a.z += n * v.z; a.w += n * v.w;
    return a;
}

__device__ __forceinline__ float4 bf4(uint2 u) {
    __nv_bfloat162 b0 = *reinterpret_cast<__nv_bfloat162*>(&u.x);
    __nv_bfloat162 b1 = *reinterpret_cast<__nv_bfloat162*>(&u.y);
    float2 f0 = __bfloat1622float2(b0);
    float2 f1 = __bfloat1622float2(b1);
    return make_float4(f0.x, f0.y, f1.x, f1.y);
}

__device__ __forceinline__ float4 gather_body(const __nv_bfloat16* __restrict__ Xb,
                                              int node, int lane) {
    float di = g_dinv[node];
    float s  = di * di;
    float4 acc = bf4(((const uint2*)(Xb + (size_t)node * D))[lane]);
    acc.x *= s; acc.y *= s; acc.z *= s; acc.w *= s;

    int beg = g_off[node], end = g_off[node + 1];
    int j = beg;
    for (; j + 8 <= end; j += 8) {             // 8-wide independent load chains
        int2 e0 = g_csr[j + 0], e1 = g_csr[j + 1];
        int2 e2 = g_csr[j + 2], e3 = g_csr[j + 3];
        int2 e4 = g_csr[j + 4], e5 = g_csr[j + 5];
        int2 e6 = g_csr[j + 6], e7 = g_csr[j + 7];
        uint2 u0 = ((const uint2*)(Xb + (size_t)e0.x * D))[lane];
        uint2 u1 = ((const uint2*)(Xb + (size_t)e1.x * D))[lane];
        uint2 u2 = ((const uint2*)(Xb + (size_t)e2.x * D))[lane];
        uint2 u3 = ((const uint2*)(Xb + (size_t)e3.x * D))[lane];
        uint2 u4 = ((const uint2*)(Xb + (size_t)e4.x * D))[lane];
        uint2 u5 = ((const uint2*)(Xb + (size_t)e5.x * D))[lane];
        uint2 u6 = ((const uint2*)(Xb + (size_t)e6.x * D))[lane];
        uint2 u7 = ((const uint2*)(Xb + (size_t)e7.x * D))[lane];
        acc = f4fma(acc, __int_as_float(e0.y), bf4(u0));
        acc = f4fma(acc, __int_as_float(e1.y), bf4(u1));
        acc = f4fma(acc, __int_as_float(e2.y), bf4(u2));
        acc = f4fma(acc, __int_as_float(e3.y), bf4(u3));
        acc = f4fma(acc, __int_as_float(e4.y), bf4(u4));
        acc = f4fma(acc, __int_as_float(e5.y), bf4(u5));
        acc = f4fma(acc, __int_as_float(e6.y), bf4(u6));
        acc = f4fma(acc, __int_as_float(e7.y), bf4(u7));
    }
    for (; j + 2 <= end; j += 2) {
        int2 e0 = g_csr[j + 0], e1 = g_csr[j + 1];
        uint2 u0 = ((const uint2*)(Xb + (size_t)e0.x * D))[lane];
        uint2 u1 = ((const uint2*)(Xb + (size_t)e1.x * D))[lane];
        acc = f4fma(acc, __int_as_float(e0.y), bf4(u0));
        acc = f4fma(acc, __int_as_float(e1.y), bf4(u1));
    }
    if (j < end) {
        int2 e = g_csr[j];
        uint2 u = ((const uint2*)(Xb + (size_t)e.x * D))[lane];
        acc = f4fma(acc, __int_as_float(e.y), bf4(u));
    }
    return acc;
}

__global__ void gather_kernel(const __nv_bfloat16* __restrict__ Xb,
                              float* __restrict__ out) {
    int node = (blockIdx.x * blockDim.x + threadIdx.x) >> 5;
    if (node >= N_NODES) return;
    int lane = threadIdx.x & 31;
    float4 acc = gather_body(Xb, node, lane);
    ((float4*)(out + (size_t)node * D))[lane] = acc;
}

// last layer: gather + pool. Interior blocks (all 8 nodes in same graph —
// batch is sorted, ~99% of blocks) reduce through smem and issue ONE warp of
// atomics per block: 12.8M contended atomics -> ~1.7M.
__global__ void gather_pool_kernel(const __nv_bfloat16* __restrict__ Xb,
                                   const int* __restrict__ batch) {
    __shared__ float sred[8][D];               // 4 KB
    int warp = threadIdx.x >> 5;               // 0..7
    int node = blockIdx.x * 8 + warp;
    int lane = threadIdx.x & 31;
    float4 acc = gather_body(Xb, node, lane);

    int g0 = batch[blockIdx.x * 8];
    int g7 = batch[blockIdx.x * 8 + 7];
    if (g0 == g7) {                            // uniform across block
        ((float4*)sred[warp])[lane] = acc;
        __syncthreads();
        if (warp == 0) {
            float4 s = make_float4(0.f, 0.f, 0.f, 0.f);
#pragma unroll
            for (int w = 0; w < 8; w++) {
                float4 v = ((float4*)sred[w])[lane];
                s.x += v.x; s.y += v.y; s.z += v.z; s.w += v.w;
            }
            float* p = &g_sums[g0 * D + lane * 4];
            atomicAdd(p + 0, s.x);
            atomicAdd(p + 1, s.y);
            atomicAdd(p + 2, s.z);
            atomicAdd(p + 3, s.w);
        }
    } else {                                   // boundary block: per-warp path
        int g = batch[node];
        float* p = &g_sums[g * D + lane * 4];
        atomicAdd(p + 0, acc.x);
        atomicAdd(p + 1, acc.y);
        atomicAdd(p + 2, acc.z);
        atomicAdd(p + 3, acc.w);
    }
}

// ---------------- head: S·W2/cnt + b2 -> linear -> softmax ----------------
__global__ void head_kernel(const float* __restrict__ W2,
                            const float* __restrict__ b2,
                            const float* __restrict__ lin_W,
                            const float* __restrict__ lin_b,
                            float* __restrict__ out) {
    __shared__ float sp[D];
    __shared__ float sl[N_CLASSES];
    int g = blockIdx.x;
    int c = threadIdx.x;
    int cnt = g_end[g] - (g > 0 ? g_end[g - 1] : 0);
    float inv = 1.0f / fmaxf((float)cnt, 1.0f);

    float acc = 0.0f;
    for (int k = 0; k < D; k++)
        acc += g_sums[g * D + k] * W2[k * D + c];
    sp[c] = acc * inv + b2[c];
    __syncthreads();

    if (c < N_CLASSES) {
        float l = lin_b[c];
        for (int k = 0; k < D; k++)
            l += sp[k] * lin_W[k * N_CLASSES + c];
        sl[c] = l;
    }
    __syncthreads();

    if (c == 0) {
        float m = sl[0];
#pragma unroll
        for (int j = 1; j < N_CLASSES; j++) m = fmaxf(m, sl[j]);
        float e[N_CLASSES], ssum = 0.0f;
#pragma unroll
        for (int j = 0; j < N_CLASSES; j++) { e[j] = expf(sl[j] - m); ssum += e[j]; }
        float isum = 1.0f / ssum;
#pragma unroll
        for (int j = 0; j < N_CLASSES; j++)
            out[g * N_CLASSES + j] = e[j] * isum;
    }
}

// ---------------- launch ----------------
extern "C" void kernel_launch(void* const* d_in, const int* in_sizes, int n_in,
                              void* d_out, int out_size) {
    const float* x     = (const float*)d_in[0];
    const int*   ei    = (const int*)d_in[1];    // int32 (JAX x64 disabled)
    const int*   batch = (const int*)d_in[2];
    const float* W0    = (const float*)d_in[3];
    const float* b0    = (const float*)d_in[4];
    const float* W1    = (const float*)d_in[5];
    const float* b1    = (const float*)d_in[6];
    const float* W2    = (const float*)d_in[7];
    const float* b2    = (const float*)d_in[8];
    const float* lW    = (const float*)d_in[9];
    const float* lb    = (const float*)d_in[10];
    float* out = (float*)d_out;

    void *ph, *phb;
    cudaGetSymbolAddress(&ph,  g_h);
    cudaGetSymbolAddress(&phb, g_hb);
    float*         A  = (float*)ph;            // fp32 agg (GEMM input)
    __nv_bfloat16* Fb = (__nv_bfloat16*)phb;   // bf16 features (gather input)

    cudaFuncSetAttribute(gemm_tc_kernel,
                         cudaFuncAttributeMaxDynamicSharedMemorySize,
                         SMEM_W_BYTES);

    const int NT = 256;
    const int node_blocks = (N_NODES + NT - 1) / NT;   // 391
    const int edge_blocks = (N_EDGES + NT - 1) / NT;
    const int gemm_blocks = N_PAD / 64;                // 1563
    const int gath_blocks = N_NODES / 8;               // warp/node, 8/block
    const int elem_blocks = (N_NODES * 32 + NT - 1) / NT;

    // CSR build + bookkeeping (graph-capturable, deterministic)
    zb_kernel<<<node_blocks, NT>>>(batch);
    hist_kernel<<<edge_blocks, NT>>>(ei + N_EDGES);
    blockred_kernel<<<node_blocks, NT>>>();
    bscan_kernel<<<1, 512>>>();
    blockscan_kernel<<<node_blocks, NT>>>();
    place_kernel<<<edge_blocks, NT>>>(ei);
    cvt_kernel<<<elem_blocks, NT>>>(x, Fb);            // x -> bf16

    // layer 0: A0 = agg(xb); Y0b = bf16(relu(A0 W0 + b0))
    gather_kernel<<<gath_blocks, NT>>>(Fb, A);
    gemm_tc_kernel<<<gemm_blocks, NT, SMEM_W_BYTES>>>(A, W0, b0, Fb);

    // layer 1: A1 = agg(Y0b); Y1b = bf16(relu(A1 W1 + b1))
    gather_kernel<<<gath_blocks, NT>>>(Fb, A);
    gemm_tc_kernel<<<gemm_blocks, NT, SMEM_W_BYTES>>>(A, W1, b1, Fb);

    // layer 2 (projection folded into head): S = pool(agg(Y1b))
    gather_pool_kernel<<<gath_blocks, NT>>>(Fb, batch);

    head_kernel<<<N_GRAPHS, D>>>(W2, b2, lW, lb, out);
}